// round 1
// baseline (speedup 1.0000x reference)
#include <cuda_runtime.h>
#include <cuda_bf16.h>
#include <cstddef>

// ---------------------------------------------------------------------------
// Problem constants
// ---------------------------------------------------------------------------
#define LEN   13294          // 100*100 + 50*50 + 25*25 + 13*13
#define BATCH 2
#define TOK   (BATCH * LEN)  // 26588
#define DMODEL 256
#define NHEAD  8
#define NLVL   4
#define NPNT   4
#define DHEAD  32
#define DFF    1024
#define LN_EPS 1e-5f

// scratch layout (floats)
#define SZ256  ((size_t)TOK * 256)   // 6,806,528
#define SZ128  ((size_t)TOK * 128)
#define SZ1024 ((size_t)TOK * 1024)

// query, value, off, attnout, x1, ln1, x2 (7 * SZ256) + attw + hid
__device__ float g_scratch[7 * SZ256 + SZ128 + SZ1024];

// ---------------------------------------------------------------------------
// Elementwise add: query = src + pos
// ---------------------------------------------------------------------------
__global__ void add_kernel(const float* __restrict__ a, const float* __restrict__ b,
                           float* __restrict__ c, int n4) {
    int i = blockIdx.x * blockDim.x + threadIdx.x;
    if (i >= n4) return;
    float4 va = ((const float4*)a)[i];
    float4 vb = ((const float4*)b)[i];
    float4 vc = make_float4(va.x + vb.x, va.y + vb.y, va.z + vb.z, va.w + vb.w);
    ((float4*)c)[i] = vc;
}

// ---------------------------------------------------------------------------
// Tiled fp32 GEMM: C[M,N] = A[M,K] @ W[K,N] + bias[N] (+ res[M,N]) (+ relu)
// BM=128, BN=128, BK=8, 256 threads, 8x8 per-thread microtile.
// N and K must be multiples of 128/8 respectively (true for all calls here).
// ---------------------------------------------------------------------------
template <bool RELU>
__global__ __launch_bounds__(256) void gemm_kernel(
    const float* __restrict__ A, const float* __restrict__ W,
    const float* __restrict__ bias, const float* __restrict__ res,
    float* __restrict__ C, int M, int N, int K)
{
    __shared__ float As[8][132];   // transposed, pad 4 -> conflict-free
    __shared__ float Bs[8][128];

    const int bm = blockIdx.y * 128;
    const int bn = blockIdx.x * 128;
    const int tid = threadIdx.x;
    const int ty = tid >> 4;        // 0..15
    const int tx = tid & 15;        // 0..15

    // global->smem load indices
    const int arow = tid >> 1;          // 0..127
    const int ac4  = (tid & 1) * 4;     // 0 or 4
    const int brow = tid >> 5;          // 0..7
    const int bc4  = (tid & 31) * 4;    // 0..124

    const bool arow_ok = (bm + arow) < M;
    const float* Aptr = A + (size_t)(bm + arow) * K + ac4;
    const float* Bptr = W + (size_t)brow * N + bn + bc4;

    float acc[8][8];
    #pragma unroll
    for (int i = 0; i < 8; ++i)
        #pragma unroll
        for (int j = 0; j < 8; ++j) acc[i][j] = 0.f;

    for (int k0 = 0; k0 < K; k0 += 8) {
        float4 av = arow_ok ? *(const float4*)(Aptr + k0) : make_float4(0.f, 0.f, 0.f, 0.f);
        float4 bv = *(const float4*)(Bptr + (size_t)k0 * N);
        As[ac4 + 0][arow] = av.x;
        As[ac4 + 1][arow] = av.y;
        As[ac4 + 2][arow] = av.z;
        As[ac4 + 3][arow] = av.w;
        *(float4*)&Bs[brow][bc4] = bv;
        __syncthreads();

        #pragma unroll
        for (int kk = 0; kk < 8; ++kk) {
            float a[8], b[8];
            *(float4*)&a[0] = *(const float4*)&As[kk][ty * 8];
            *(float4*)&a[4] = *(const float4*)&As[kk][ty * 8 + 4];
            *(float4*)&b[0] = *(const float4*)&Bs[kk][tx * 8];
            *(float4*)&b[4] = *(const float4*)&Bs[kk][tx * 8 + 4];
            #pragma unroll
            for (int i = 0; i < 8; ++i)
                #pragma unroll
                for (int j = 0; j < 8; ++j)
                    acc[i][j] = fmaf(a[i], b[j], acc[i][j]);
        }
        __syncthreads();
    }

    // epilogue
    #pragma unroll
    for (int i = 0; i < 8; ++i) {
        int row = bm + ty * 8 + i;
        if (row >= M) break;
        #pragma unroll
        for (int j4 = 0; j4 < 8; j4 += 4) {
            int col = bn + tx * 8 + j4;
            float4 v = make_float4(acc[i][j4], acc[i][j4 + 1], acc[i][j4 + 2], acc[i][j4 + 3]);
            float4 bb = *(const float4*)&bias[col];
            v.x += bb.x; v.y += bb.y; v.z += bb.z; v.w += bb.w;
            if (res) {
                float4 rr = *(const float4*)&res[(size_t)row * N + col];
                v.x += rr.x; v.y += rr.y; v.z += rr.z; v.w += rr.w;
            }
            if (RELU) {
                v.x = fmaxf(v.x, 0.f); v.y = fmaxf(v.y, 0.f);
                v.z = fmaxf(v.z, 0.f); v.w = fmaxf(v.w, 0.f);
            }
            *(float4*)&C[(size_t)row * N + col] = v;
        }
    }
}

// ---------------------------------------------------------------------------
// Softmax over contiguous groups of 16 (one thread per row of 16)
// ---------------------------------------------------------------------------
__global__ void softmax16_kernel(float* __restrict__ x, int nrows) {
    int r = blockIdx.x * blockDim.x + threadIdx.x;
    if (r >= nrows) return;
    float* p = x + (size_t)r * 16;
    float v[16];
    *(float4*)&v[0]  = *(const float4*)(p + 0);
    *(float4*)&v[4]  = *(const float4*)(p + 4);
    *(float4*)&v[8]  = *(const float4*)(p + 8);
    *(float4*)&v[12] = *(const float4*)(p + 12);
    float m = v[0];
    #pragma unroll
    for (int i = 1; i < 16; ++i) m = fmaxf(m, v[i]);
    float s = 0.f;
    #pragma unroll
    for (int i = 0; i < 16; ++i) { v[i] = __expf(v[i] - m); s += v[i]; }
    float inv = 1.f / s;
    #pragma unroll
    for (int i = 0; i < 16; ++i) v[i] *= inv;
    *(float4*)(p + 0)  = *(float4*)&v[0];
    *(float4*)(p + 4)  = *(float4*)&v[4];
    *(float4*)(p + 8)  = *(float4*)&v[8];
    *(float4*)(p + 12) = *(float4*)&v[12];
}

// ---------------------------------------------------------------------------
// Deformable sampling: one warp per (token, head), lane = channel (DHEAD=32)
// out[tok, h*32+c] = sum_{l,p} attw * bilinear(value level l at loc)
// ---------------------------------------------------------------------------
__global__ void sample_kernel(const float* __restrict__ value,
                              const float* __restrict__ off,
                              const float* __restrict__ attw,
                              const float* __restrict__ ref,
                              float* __restrict__ out) {
    int gtid = blockIdx.x * blockDim.x + threadIdx.x;
    int gw = gtid >> 5;
    int lane = gtid & 31;
    if (gw >= TOK * NHEAD) return;
    int q = gw >> 3;      // token index 0..TOK-1
    int h = gw & 7;
    int b = q / LEN;

    const int HS[4] = {100, 50, 25, 13};
    const int ST[4] = {0, 10000, 12500, 13125};

    const float* offp = off + (size_t)q * 256 + h * 32;
    const float* awp  = attw + (size_t)q * 128 + h * 16;
    const float* refp = ref + (size_t)q * 8;
    const float* vb   = value + (size_t)b * LEN * 256 + h * 32 + lane;

    float acc = 0.f;
    #pragma unroll
    for (int l = 0; l < 4; ++l) {
        const int Hl = HS[l];          // square levels: W == H
        const int st = ST[l];
        float rx = refp[l * 2 + 0];
        float ry = refp[l * 2 + 1];
        #pragma unroll
        for (int p = 0; p < 4; ++p) {
            float ox = offp[(l * 4 + p) * 2 + 0];
            float oy = offp[(l * 4 + p) * 2 + 1];
            float w  = awp[l * 4 + p];
            float x = rx * (float)Hl + ox - 0.5f;
            float y = ry * (float)Hl + oy - 0.5f;
            float x0f = floorf(x), y0f = floorf(y);
            int x0 = (int)x0f, y0 = (int)y0f;
            float dx = x - x0f, dy = y - y0f;

            float s = 0.f;
            bool xin0 = (x0 >= 0) && (x0 < Hl);
            bool xin1 = (x0 + 1 >= 0) && (x0 + 1 < Hl);
            bool yin0 = (y0 >= 0) && (y0 < Hl);
            bool yin1 = (y0 + 1 >= 0) && (y0 + 1 < Hl);
            if (yin0) {
                int rowb = st + y0 * Hl;
                if (xin0) s += (1.f - dx) * (1.f - dy) * vb[(size_t)(rowb + x0) * 256];
                if (xin1) s += dx * (1.f - dy) * vb[(size_t)(rowb + x0 + 1) * 256];
            }
            if (yin1) {
                int rowb = st + (y0 + 1) * Hl;
                if (xin0) s += (1.f - dx) * dy * vb[(size_t)(rowb + x0) * 256];
                if (xin1) s += dx * dy * vb[(size_t)(rowb + x0 + 1) * 256];
            }
            acc = fmaf(w, s, acc);
        }
    }
    out[(size_t)q * 256 + h * 32 + lane] = acc;
}

// ---------------------------------------------------------------------------
// LayerNorm over D=256: one warp per row, 8 elems per lane
// ---------------------------------------------------------------------------
__global__ void ln_kernel(const float* __restrict__ x, const float* __restrict__ g,
                          const float* __restrict__ be, float* __restrict__ y,
                          int nrows) {
    int gtid = blockIdx.x * blockDim.x + threadIdx.x;
    int row = gtid >> 5;
    int lane = gtid & 31;
    if (row >= nrows) return;
    const float* p = x + (size_t)row * 256 + lane * 8;
    float v[8];
    *(float4*)&v[0] = *(const float4*)(p + 0);
    *(float4*)&v[4] = *(const float4*)(p + 4);
    float s = 0.f;
    #pragma unroll
    for (int i = 0; i < 8; ++i) s += v[i];
    #pragma unroll
    for (int o = 16; o > 0; o >>= 1) s += __shfl_xor_sync(0xffffffffu, s, o);
    float mean = s * (1.f / 256.f);
    float vs = 0.f;
    #pragma unroll
    for (int i = 0; i < 8; ++i) { float d = v[i] - mean; vs += d * d; }
    #pragma unroll
    for (int o = 16; o > 0; o >>= 1) vs += __shfl_xor_sync(0xffffffffu, vs, o);
    float rstd = rsqrtf(vs * (1.f / 256.f) + LN_EPS);
    float* q = y + (size_t)row * 256 + lane * 8;
    const float* gp = g + lane * 8;
    const float* bp = be + lane * 8;
    float go[8], bo[8];
    *(float4*)&go[0] = *(const float4*)(gp + 0);
    *(float4*)&go[4] = *(const float4*)(gp + 4);
    *(float4*)&bo[0] = *(const float4*)(bp + 0);
    *(float4*)&bo[4] = *(const float4*)(bp + 4);
    #pragma unroll
    for (int i = 0; i < 8; ++i) v[i] = (v[i] - mean) * rstd * go[i] + bo[i];
    *(float4*)(q + 0) = *(float4*)&v[0];
    *(float4*)(q + 4) = *(float4*)&v[4];
}

// ---------------------------------------------------------------------------
// Host launch
// ---------------------------------------------------------------------------
extern "C" void kernel_launch(void* const* d_in, const int* in_sizes, int n_in,
                              void* d_out, int out_size) {
    const float* src     = (const float*)d_in[0];
    const float* pos     = (const float*)d_in[1];
    const float* refpts  = (const float*)d_in[2];
    const float* W_value = (const float*)d_in[3];
    const float* b_value = (const float*)d_in[4];
    const float* W_off   = (const float*)d_in[5];
    const float* b_off   = (const float*)d_in[6];
    const float* W_attn  = (const float*)d_in[7];
    const float* b_attn  = (const float*)d_in[8];
    const float* W_out   = (const float*)d_in[9];
    const float* b_out   = (const float*)d_in[10];
    const float* W1      = (const float*)d_in[11];
    const float* b1      = (const float*)d_in[12];
    const float* W2      = (const float*)d_in[13];
    const float* b2      = (const float*)d_in[14];
    const float* g1      = (const float*)d_in[15];
    const float* be1     = (const float*)d_in[16];
    const float* g2      = (const float*)d_in[17];
    const float* be2     = (const float*)d_in[18];
    float* out = (float*)d_out;

    void* sp = nullptr;
    cudaGetSymbolAddress(&sp, g_scratch);
    float* base    = (float*)sp;
    float* g_query   = base;
    float* g_value   = g_query   + SZ256;
    float* g_off     = g_value   + SZ256;
    float* g_attnout = g_off     + SZ256;
    float* g_x1      = g_attnout + SZ256;
    float* g_ln1     = g_x1      + SZ256;
    float* g_x2      = g_ln1     + SZ256;
    float* g_attw    = g_x2      + SZ256;
    float* g_hid     = g_attw    + SZ128;

    const int M = TOK;
    const int gy = (M + 127) / 128;   // 208

    // 1) query = src + pos
    {
        int n4 = (int)(SZ256 / 4);
        add_kernel<<<(n4 + 255) / 256, 256>>>(src, pos, g_query, n4);
    }
    // 2) value = src @ W_value + b_value        [M,256,256]
    gemm_kernel<false><<<dim3(256 / 128, gy), 256>>>(src, W_value, b_value, nullptr, g_value, M, 256, 256);
    // 3) off = query @ W_off + b_off            [M,256,256]
    gemm_kernel<false><<<dim3(256 / 128, gy), 256>>>(g_query, W_off, b_off, nullptr, g_off, M, 256, 256);
    // 4) attw logits = query @ W_attn + b_attn  [M,128,256]
    gemm_kernel<false><<<dim3(128 / 128, gy), 256>>>(g_query, W_attn, b_attn, nullptr, g_attw, M, 128, 256);
    // 5) softmax over groups of 16
    {
        int nrows = TOK * NHEAD;
        softmax16_kernel<<<(nrows + 255) / 256, 256>>>(g_attw, nrows);
    }
    // 6) deformable sampling
    {
        int nthreads = TOK * NHEAD * 32;
        sample_kernel<<<(nthreads + 255) / 256, 256>>>(g_value, g_off, g_attw, refpts, g_attnout);
    }
    // 7) x1 = attnout @ W_out + b_out + src     [M,256,256]
    gemm_kernel<false><<<dim3(256 / 128, gy), 256>>>(g_attnout, W_out, b_out, src, g_x1, M, 256, 256);
    // 8) ln1 = LN(x1)
    {
        int nthreads = TOK * 32;
        ln_kernel<<<(nthreads + 255) / 256, 256>>>(g_x1, g1, be1, g_ln1, TOK);
    }
    // 9) hid = relu(ln1 @ W1 + b1)              [M,1024,256]
    gemm_kernel<true><<<dim3(1024 / 128, gy), 256>>>(g_ln1, W1, b1, nullptr, g_hid, M, 1024, 256);
    // 10) x2 = hid @ W2 + b2 + ln1              [M,256,1024]
    gemm_kernel<false><<<dim3(256 / 128, gy), 256>>>(g_hid, W2, b2, g_ln1, g_x2, M, 256, 1024);
    // 11) out = LN(x2)
    {
        int nthreads = TOK * 32;
        ln_kernel<<<(nthreads + 255) / 256, 256>>>(g_x2, g2, be2, out, TOK);
    }
}

// round 2
// speedup vs baseline: 1.9916x; 1.9916x over previous
#include <cuda_runtime.h>
#include <cuda_bf16.h>
#include <cstdint>
#include <cstddef>

// ---------------------------------------------------------------------------
// Problem constants
// ---------------------------------------------------------------------------
#define LEN   13294          // 100*100 + 50*50 + 25*25 + 13*13
#define BATCH 2
#define TOK   (BATCH * LEN)  // 26588
#define NHEAD  8
#define LN_EPS 1e-5f

#define SZ256  ((size_t)TOK * 256)
#define SZ128  ((size_t)TOK * 128)
#define SZ1024 ((size_t)TOK * 1024)

__device__ float g_scratch[7 * SZ256 + SZ128 + SZ1024];

// ---------------------------------------------------------------------------
// Elementwise add
// ---------------------------------------------------------------------------
__global__ void add_kernel(const float* __restrict__ a, const float* __restrict__ b,
                           float* __restrict__ c, int n4) {
    int i = blockIdx.x * blockDim.x + threadIdx.x;
    if (i >= n4) return;
    float4 va = ((const float4*)a)[i];
    float4 vb = ((const float4*)b)[i];
    ((float4*)c)[i] = make_float4(va.x + vb.x, va.y + vb.y, va.z + vb.z, va.w + vb.w);
}

// ---------------------------------------------------------------------------
// TF32 tensor-core GEMM: C[M,N] = A[M,K] @ W[K,N] + bias (+res) (+relu)
// Block tile 128x128, BK=16, 256 threads (8 warps), warp tile 64x32.
// mma.sync.m16n8k8 tf32, fp32 accumulate. Double-buffered smem.
// N, K multiples of 128/16 (true for all calls). M may be ragged.
// ---------------------------------------------------------------------------
__device__ __forceinline__ uint32_t f2tf32(float x) {
    uint32_t r;
    asm("cvt.rna.tf32.f32 %0, %1;" : "=r"(r) : "f"(x));
    return r;
}

#define MMA_TF32(d, a, b)                                                     \
    asm volatile(                                                             \
        "mma.sync.aligned.m16n8k8.row.col.f32.tf32.tf32.f32 "                 \
        "{%0,%1,%2,%3},{%4,%5,%6,%7},{%8,%9},{%0,%1,%2,%3};"                  \
        : "+f"(d[0]), "+f"(d[1]), "+f"(d[2]), "+f"(d[3])                      \
        : "r"(a[0]), "r"(a[1]), "r"(a[2]), "r"(a[3]), "r"(b[0]), "r"(b[1]))

#define AS_STRIDE 20   // 16 + 4 pad -> conflict-free frag loads
#define BS_STRIDE 136  // 128 + 8 pad -> conflict-free frag loads

template <bool RELU>
__global__ __launch_bounds__(256) void gemm_tc(
    const float* __restrict__ A, const float* __restrict__ W,
    const float* __restrict__ bias, const float* __restrict__ res,
    float* __restrict__ C, int M, int N, int K)
{
    __shared__ uint32_t As[2][128 * AS_STRIDE];
    __shared__ uint32_t Bs[2][16 * BS_STRIDE];

    const int bm = blockIdx.y * 128;
    const int bn = blockIdx.x * 128;
    const int tid = threadIdx.x;
    const int wid = tid >> 5, lane = tid & 31;
    const int wm = (wid & 1) * 64;        // warp m offset
    const int wn = (wid >> 1) * 32;       // warp n offset
    const int g = lane >> 2, tg = lane & 3;

    // gmem->smem loader mapping
    const int arow = tid >> 1;            // 0..127
    const int acol = (tid & 1) * 8;       // 0 or 8
    const int brow = tid >> 4;            // 0..15
    const int bcol = (tid & 15) * 8;      // 0..120
    const bool aok = (bm + arow) < M;
    const float* Ap = A + (size_t)(bm + arow) * K + acol;
    const float* Bp = W + (size_t)brow * N + bn + bcol;

    float acc[4][4][4];
    #pragma unroll
    for (int mi = 0; mi < 4; ++mi)
        #pragma unroll
        for (int ni = 0; ni < 4; ++ni)
            #pragma unroll
            for (int e = 0; e < 4; ++e) acc[mi][ni][e] = 0.f;

    const int nst = K >> 4;
    float rA[8], rB[8];

    // ---- prologue: stage 0 ----
    {
        if (aok) {
            float4 a0 = *(const float4*)(Ap);
            float4 a1 = *(const float4*)(Ap + 4);
            rA[0] = a0.x; rA[1] = a0.y; rA[2] = a0.z; rA[3] = a0.w;
            rA[4] = a1.x; rA[5] = a1.y; rA[6] = a1.z; rA[7] = a1.w;
        } else {
            #pragma unroll
            for (int i = 0; i < 8; ++i) rA[i] = 0.f;
        }
        float4 b0 = *(const float4*)(Bp);
        float4 b1 = *(const float4*)(Bp + 4);
        rB[0] = b0.x; rB[1] = b0.y; rB[2] = b0.z; rB[3] = b0.w;
        rB[4] = b1.x; rB[5] = b1.y; rB[6] = b1.z; rB[7] = b1.w;

        uint32_t* as = &As[0][arow * AS_STRIDE + acol];
        uint32_t* bs = &Bs[0][brow * BS_STRIDE + bcol];
        uint4 pa0 = make_uint4(f2tf32(rA[0]), f2tf32(rA[1]), f2tf32(rA[2]), f2tf32(rA[3]));
        uint4 pa1 = make_uint4(f2tf32(rA[4]), f2tf32(rA[5]), f2tf32(rA[6]), f2tf32(rA[7]));
        uint4 pb0 = make_uint4(f2tf32(rB[0]), f2tf32(rB[1]), f2tf32(rB[2]), f2tf32(rB[3]));
        uint4 pb1 = make_uint4(f2tf32(rB[4]), f2tf32(rB[5]), f2tf32(rB[6]), f2tf32(rB[7]));
        *(uint4*)(as) = pa0; *(uint4*)(as + 4) = pa1;
        *(uint4*)(bs) = pb0; *(uint4*)(bs + 4) = pb1;
    }
    __syncthreads();

    for (int s = 0; s < nst; ++s) {
        const int cur = s & 1;
        const bool more = (s + 1) < nst;

        // prefetch next stage into registers
        if (more) {
            const int k0 = (s + 1) << 4;
            if (aok) {
                float4 a0 = *(const float4*)(Ap + k0);
                float4 a1 = *(const float4*)(Ap + k0 + 4);
                rA[0] = a0.x; rA[1] = a0.y; rA[2] = a0.z; rA[3] = a0.w;
                rA[4] = a1.x; rA[5] = a1.y; rA[6] = a1.z; rA[7] = a1.w;
            } else {
                #pragma unroll
                for (int i = 0; i < 8; ++i) rA[i] = 0.f;
            }
            const float* bp = Bp + (size_t)k0 * N;
            float4 b0 = *(const float4*)(bp);
            float4 b1 = *(const float4*)(bp + 4);
            rB[0] = b0.x; rB[1] = b0.y; rB[2] = b0.z; rB[3] = b0.w;
            rB[4] = b1.x; rB[5] = b1.y; rB[6] = b1.z; rB[7] = b1.w;
        }

        // compute current stage (two k8 sub-steps)
        const uint32_t* asb = As[cur];
        const uint32_t* bsb = Bs[cur];
        #pragma unroll
        for (int kk = 0; kk < 16; kk += 8) {
            uint32_t a[4][4], b[4][2];
            #pragma unroll
            for (int mi = 0; mi < 4; ++mi) {
                int base = (wm + mi * 16 + g) * AS_STRIDE + kk + tg;
                a[mi][0] = asb[base];
                a[mi][1] = asb[base + 8 * AS_STRIDE];
                a[mi][2] = asb[base + 4];
                a[mi][3] = asb[base + 8 * AS_STRIDE + 4];
            }
            #pragma unroll
            for (int ni = 0; ni < 4; ++ni) {
                int c = wn + ni * 8 + g;
                b[ni][0] = bsb[(kk + tg) * BS_STRIDE + c];
                b[ni][1] = bsb[(kk + tg + 4) * BS_STRIDE + c];
            }
            #pragma unroll
            for (int mi = 0; mi < 4; ++mi)
                #pragma unroll
                for (int ni = 0; ni < 4; ++ni)
                    MMA_TF32(acc[mi][ni], a[mi], b[ni]);
        }

        // store prefetched stage
        if (more) {
            const int nxt = cur ^ 1;
            uint32_t* as = &As[nxt][arow * AS_STRIDE + acol];
            uint32_t* bs = &Bs[nxt][brow * BS_STRIDE + bcol];
            uint4 pa0 = make_uint4(f2tf32(rA[0]), f2tf32(rA[1]), f2tf32(rA[2]), f2tf32(rA[3]));
            uint4 pa1 = make_uint4(f2tf32(rA[4]), f2tf32(rA[5]), f2tf32(rA[6]), f2tf32(rA[7]));
            uint4 pb0 = make_uint4(f2tf32(rB[0]), f2tf32(rB[1]), f2tf32(rB[2]), f2tf32(rB[3]));
            uint4 pb1 = make_uint4(f2tf32(rB[4]), f2tf32(rB[5]), f2tf32(rB[6]), f2tf32(rB[7]));
            *(uint4*)(as) = pa0; *(uint4*)(as + 4) = pa1;
            *(uint4*)(bs) = pb0; *(uint4*)(bs + 4) = pb1;
        }
        __syncthreads();
    }

    // ---- epilogue ----
    #pragma unroll
    for (int mi = 0; mi < 4; ++mi) {
        int r0 = bm + wm + mi * 16 + g;
        int r1 = r0 + 8;
        #pragma unroll
        for (int ni = 0; ni < 4; ++ni) {
            int col = bn + wn + ni * 8 + 2 * tg;
            float2 bb = *(const float2*)&bias[col];
            if (r0 < M) {
                float2 v = make_float2(acc[mi][ni][0] + bb.x, acc[mi][ni][1] + bb.y);
                if (res) {
                    float2 rr = *(const float2*)&res[(size_t)r0 * N + col];
                    v.x += rr.x; v.y += rr.y;
                }
                if (RELU) { v.x = fmaxf(v.x, 0.f); v.y = fmaxf(v.y, 0.f); }
                *(float2*)&C[(size_t)r0 * N + col] = v;
            }
            if (r1 < M) {
                float2 v = make_float2(acc[mi][ni][2] + bb.x, acc[mi][ni][3] + bb.y);
                if (res) {
                    float2 rr = *(const float2*)&res[(size_t)r1 * N + col];
                    v.x += rr.x; v.y += rr.y;
                }
                if (RELU) { v.x = fmaxf(v.x, 0.f); v.y = fmaxf(v.y, 0.f); }
                *(float2*)&C[(size_t)r1 * N + col] = v;
            }
        }
    }
}

// ---------------------------------------------------------------------------
// Softmax over contiguous groups of 16
// ---------------------------------------------------------------------------
__global__ void softmax16_kernel(float* __restrict__ x, int nrows) {
    int r = blockIdx.x * blockDim.x + threadIdx.x;
    if (r >= nrows) return;
    float* p = x + (size_t)r * 16;
    float v[16];
    *(float4*)&v[0]  = *(const float4*)(p + 0);
    *(float4*)&v[4]  = *(const float4*)(p + 4);
    *(float4*)&v[8]  = *(const float4*)(p + 8);
    *(float4*)&v[12] = *(const float4*)(p + 12);
    float m = v[0];
    #pragma unroll
    for (int i = 1; i < 16; ++i) m = fmaxf(m, v[i]);
    float s = 0.f;
    #pragma unroll
    for (int i = 0; i < 16; ++i) { v[i] = __expf(v[i] - m); s += v[i]; }
    float inv = 1.f / s;
    #pragma unroll
    for (int i = 0; i < 16; ++i) v[i] *= inv;
    *(float4*)(p + 0)  = *(float4*)&v[0];
    *(float4*)(p + 4)  = *(float4*)&v[4];
    *(float4*)(p + 8)  = *(float4*)&v[8];
    *(float4*)(p + 12) = *(float4*)&v[12];
}

// ---------------------------------------------------------------------------
// Deformable sampling, branchless: one warp per (token, head), lane = channel
// ---------------------------------------------------------------------------
__global__ void sample_kernel(const float* __restrict__ value,
                              const float* __restrict__ off,
                              const float* __restrict__ attw,
                              const float* __restrict__ ref,
                              float* __restrict__ out) {
    int gtid = blockIdx.x * blockDim.x + threadIdx.x;
    int gw = gtid >> 5;
    int lane = gtid & 31;
    if (gw >= TOK * NHEAD) return;
    int q = gw >> 3;
    int h = gw & 7;
    int b = q / LEN;

    const int HS[4] = {100, 50, 25, 13};
    const int ST[4] = {0, 10000, 12500, 13125};

    const float* offp = off + (size_t)q * 256 + h * 32;
    const float* awp  = attw + (size_t)q * 128 + h * 16;
    const float* refp = ref + (size_t)q * 8;
    const float* vb   = value + (size_t)b * LEN * 256 + h * 32 + lane;

    float acc = 0.f;
    #pragma unroll
    for (int l = 0; l < 4; ++l) {
        const int Hl = HS[l];
        const int st = ST[l];
        float rx = refp[l * 2 + 0];
        float ry = refp[l * 2 + 1];
        #pragma unroll
        for (int p = 0; p < 4; ++p) {
            float ox = offp[(l * 4 + p) * 2 + 0];
            float oy = offp[(l * 4 + p) * 2 + 1];
            float w  = awp[l * 4 + p];
            float x = fmaf(rx, (float)Hl, ox - 0.5f);
            float y = fmaf(ry, (float)Hl, oy - 0.5f);
            float x0f = floorf(x), y0f = floorf(y);
            int x0 = (int)x0f, y0 = (int)y0f;
            float dx = x - x0f, dy = y - y0f;

            // in-bounds masks as floats
            float mx0 = (x0 >= 0 && x0 < Hl) ? 1.f : 0.f;
            float mx1 = (x0 + 1 >= 0 && x0 + 1 < Hl) ? 1.f : 0.f;
            float my0 = (y0 >= 0 && y0 < Hl) ? 1.f : 0.f;
            float my1 = (y0 + 1 >= 0 && y0 + 1 < Hl) ? 1.f : 0.f;

            int x0c = min(max(x0, 0), Hl - 1);
            int x1c = min(max(x0 + 1, 0), Hl - 1);
            int y0c = min(max(y0, 0), Hl - 1);
            int y1c = min(max(y0 + 1, 0), Hl - 1);

            float w00 = (1.f - dx) * (1.f - dy) * mx0 * my0;
            float w10 = dx * (1.f - dy) * mx1 * my0;
            float w01 = (1.f - dx) * dy * mx0 * my1;
            float w11 = dx * dy * mx1 * my1;

            int r0 = st + y0c * Hl;
            int r1 = st + y1c * Hl;
            float v00 = vb[(size_t)(r0 + x0c) * 256];
            float v10 = vb[(size_t)(r0 + x1c) * 256];
            float v01 = vb[(size_t)(r1 + x0c) * 256];
            float v11 = vb[(size_t)(r1 + x1c) * 256];

            float s = w00 * v00 + w10 * v10 + w01 * v01 + w11 * v11;
            acc = fmaf(w, s, acc);
        }
    }
    out[(size_t)q * 256 + h * 32 + lane] = acc;
}

// ---------------------------------------------------------------------------
// LayerNorm over D=256: one warp per row
// ---------------------------------------------------------------------------
__global__ void ln_kernel(const float* __restrict__ x, const float* __restrict__ g,
                          const float* __restrict__ be, float* __restrict__ y,
                          int nrows) {
    int gtid = blockIdx.x * blockDim.x + threadIdx.x;
    int row = gtid >> 5;
    int lane = gtid & 31;
    if (row >= nrows) return;
    const float* p = x + (size_t)row * 256 + lane * 8;
    float v[8];
    *(float4*)&v[0] = *(const float4*)(p + 0);
    *(float4*)&v[4] = *(const float4*)(p + 4);
    float s = 0.f;
    #pragma unroll
    for (int i = 0; i < 8; ++i) s += v[i];
    #pragma unroll
    for (int o = 16; o > 0; o >>= 1) s += __shfl_xor_sync(0xffffffffu, s, o);
    float mean = s * (1.f / 256.f);
    float vs = 0.f;
    #pragma unroll
    for (int i = 0; i < 8; ++i) { float d = v[i] - mean; vs += d * d; }
    #pragma unroll
    for (int o = 16; o > 0; o >>= 1) vs += __shfl_xor_sync(0xffffffffu, vs, o);
    float rstd = rsqrtf(vs * (1.f / 256.f) + LN_EPS);
    float* q = y + (size_t)row * 256 + lane * 8;
    const float* gp = g + lane * 8;
    const float* bp = be + lane * 8;
    float go[8], bo[8];
    *(float4*)&go[0] = *(const float4*)(gp + 0);
    *(float4*)&go[4] = *(const float4*)(gp + 4);
    *(float4*)&bo[0] = *(const float4*)(bp + 0);
    *(float4*)&bo[4] = *(const float4*)(bp + 4);
    #pragma unroll
    for (int i = 0; i < 8; ++i) v[i] = (v[i] - mean) * rstd * go[i] + bo[i];
    *(float4*)(q + 0) = *(float4*)&v[0];
    *(float4*)(q + 4) = *(float4*)&v[4];
}

// ---------------------------------------------------------------------------
// Host launch
// ---------------------------------------------------------------------------
extern "C" void kernel_launch(void* const* d_in, const int* in_sizes, int n_in,
                              void* d_out, int out_size) {
    const float* src     = (const float*)d_in[0];
    const float* pos     = (const float*)d_in[1];
    const float* refpts  = (const float*)d_in[2];
    const float* W_value = (const float*)d_in[3];
    const float* b_value = (const float*)d_in[4];
    const float* W_off   = (const float*)d_in[5];
    const float* b_off   = (const float*)d_in[6];
    const float* W_attn  = (const float*)d_in[7];
    const float* b_attn  = (const float*)d_in[8];
    const float* W_out   = (const float*)d_in[9];
    const float* b_out   = (const float*)d_in[10];
    const float* W1      = (const float*)d_in[11];
    const float* b1      = (const float*)d_in[12];
    const float* W2      = (const float*)d_in[13];
    const float* b2      = (const float*)d_in[14];
    const float* g1      = (const float*)d_in[15];
    const float* be1     = (const float*)d_in[16];
    const float* g2      = (const float*)d_in[17];
    const float* be2     = (const float*)d_in[18];
    float* out = (float*)d_out;

    void* sp = nullptr;
    cudaGetSymbolAddress(&sp, g_scratch);
    float* base      = (float*)sp;
    float* g_query   = base;
    float* g_value   = g_query   + SZ256;
    float* g_off     = g_value   + SZ256;
    float* g_attnout = g_off     + SZ256;
    float* g_x1      = g_attnout + SZ256;
    float* g_ln1     = g_x1      + SZ256;
    float* g_x2      = g_ln1     + SZ256;
    float* g_attw    = g_x2      + SZ256;
    float* g_hid     = g_attw    + SZ128;

    const int M = TOK;
    const int gy = (M + 127) / 128;   // 208

    // 1) query = src + pos
    {
        int n4 = (int)(SZ256 / 4);
        add_kernel<<<(n4 + 255) / 256, 256>>>(src, pos, g_query, n4);
    }
    // 2) value = src @ W_value + b_value
    gemm_tc<false><<<dim3(2, gy), 256>>>(src, W_value, b_value, nullptr, g_value, M, 256, 256);
    // 3) off = query @ W_off + b_off
    gemm_tc<false><<<dim3(2, gy), 256>>>(g_query, W_off, b_off, nullptr, g_off, M, 256, 256);
    // 4) attw logits = query @ W_attn + b_attn
    gemm_tc<false><<<dim3(1, gy), 256>>>(g_query, W_attn, b_attn, nullptr, g_attw, M, 128, 256);
    // 5) softmax over groups of 16
    {
        int nrows = TOK * NHEAD;
        softmax16_kernel<<<(nrows + 255) / 256, 256>>>(g_attw, nrows);
    }
    // 6) deformable sampling
    {
        int nthreads = TOK * NHEAD * 32;
        sample_kernel<<<(nthreads + 255) / 256, 256>>>(g_value, g_off, g_attw, refpts, g_attnout);
    }
    // 7) x1 = attnout @ W_out + b_out + src
    gemm_tc<false><<<dim3(2, gy), 256>>>(g_attnout, W_out, b_out, src, g_x1, M, 256, 256);
    // 8) ln1 = LN(x1)
    {
        int nthreads = TOK * 32;
        ln_kernel<<<(nthreads + 255) / 256, 256>>>(g_x1, g1, be1, g_ln1, TOK);
    }
    // 9) hid = relu(ln1 @ W1 + b1)
    gemm_tc<true><<<dim3(8, gy), 256>>>(g_ln1, W1, b1, nullptr, g_hid, M, 1024, 256);
    // 10) x2 = hid @ W2 + b2 + ln1
    gemm_tc<false><<<dim3(2, gy), 256>>>(g_hid, W2, b2, g_ln1, g_x2, M, 256, 1024);
    // 11) out = LN(x2)
    {
        int nthreads = TOK * 32;
        ln_kernel<<<(nthreads + 255) / 256, 256>>>(g_x2, g2, be2, out, TOK);
    }
}

// round 5
// speedup vs baseline: 2.1235x; 1.0662x over previous
#include <cuda_runtime.h>
#include <cuda_fp16.h>
#include <cuda_bf16.h>
#include <cstdint>
#include <cstddef>

// ---------------------------------------------------------------------------
// Problem constants
// ---------------------------------------------------------------------------
#define LEN   13294          // 100*100 + 50*50 + 25*25 + 13*13
#define BATCH 2
#define TOK   (BATCH * LEN)  // 26588
#define NHEAD  8
#define LN_EPS 1e-5f

#define SZ256  ((size_t)TOK * 256)
#define SZ128  ((size_t)TOK * 128)
#define SZ1024 ((size_t)TOK * 1024)

__device__ float g_scratch[7 * SZ256 + SZ128 + SZ1024];

// ---------------------------------------------------------------------------
// Elementwise add
// ---------------------------------------------------------------------------
__global__ void add_kernel(const float* __restrict__ a, const float* __restrict__ b,
                           float* __restrict__ c, int n4) {
    int i = blockIdx.x * blockDim.x + threadIdx.x;
    if (i >= n4) return;
    float4 va = ((const float4*)a)[i];
    float4 vb = ((const float4*)b)[i];
    ((float4*)c)[i] = make_float4(va.x + vb.x, va.y + vb.y, va.z + vb.z, va.w + vb.w);
}

// ---------------------------------------------------------------------------
// cp.async helpers
// ---------------------------------------------------------------------------
__device__ __forceinline__ void cp_async16(void* smem, const void* gmem, bool pred) {
    uint32_t s = (uint32_t)__cvta_generic_to_shared(smem);
    int sz = pred ? 16 : 0;
    asm volatile("cp.async.cg.shared.global [%0], [%1], 16, %2;\n"
                 :: "r"(s), "l"(gmem), "r"(sz));
}
__device__ __forceinline__ void cp_commit() {
    asm volatile("cp.async.commit_group;\n" ::);
}
template <int N>
__device__ __forceinline__ void cp_wait() {
    asm volatile("cp.async.wait_group %0;\n" :: "n"(N));
}

#define MMA_TF32(d, a, b)                                                     \
    asm volatile(                                                             \
        "mma.sync.aligned.m16n8k8.row.col.f32.tf32.tf32.f32 "                 \
        "{%0,%1,%2,%3},{%4,%5,%6,%7},{%8,%9},{%0,%1,%2,%3};"                  \
        : "+f"(d[0]), "+f"(d[1]), "+f"(d[2]), "+f"(d[3])                      \
        : "r"(a[0]), "r"(a[1]), "r"(a[2]), "r"(a[3]), "r"(b[0]), "r"(b[1]))

// ---------------------------------------------------------------------------
// TF32 tensor-core GEMM with 4-stage cp.async pipeline, dynamic smem.
// C[M,N] = A[M,K] @ W[K,N] + bias (+res) (+relu). fp32 bits in smem;
// HMMA.TF32 truncates the mantissa in HW (no cvt needed).
// Block tile 128x128, BK=16, 256 threads (8 warps), warp tile 64x32.
// ---------------------------------------------------------------------------
#define AS_STRIDE 20   // 16 + 4 pad -> conflict-free frag loads
#define BS_STRIDE 136  // 128 + 8 pad -> conflict-free frag loads
#define STAGES 4
#define AS_ELEMS (128 * AS_STRIDE)          // per stage
#define BS_ELEMS (16 * BS_STRIDE)           // per stage
#define GEMM_SMEM_BYTES (STAGES * (AS_ELEMS + BS_ELEMS) * 4)   // 75,776

template <bool RELU, typename OutT>
__global__ __launch_bounds__(256) void gemm_tc(
    const float* __restrict__ A, const float* __restrict__ W,
    const float* __restrict__ bias, const float* __restrict__ res,
    OutT* __restrict__ C, int M, int N, int K)
{
    extern __shared__ float smem[];
    float* AsBase = smem;                        // STAGES * AS_ELEMS
    float* BsBase = smem + STAGES * AS_ELEMS;    // STAGES * BS_ELEMS

    const int bm = blockIdx.y * 128;
    const int bn = blockIdx.x * 128;
    const int tid = threadIdx.x;
    const int wid = tid >> 5, lane = tid & 31;
    const int wm = (wid & 1) * 64;
    const int wn = (wid >> 1) * 32;
    const int g = lane >> 2, tg = lane & 3;

    const int arow = tid >> 1;            // 0..127
    const int acol = (tid & 1) * 8;       // 0 or 8
    const int brow = tid >> 4;            // 0..15
    const int bcol = (tid & 15) * 8;      // 0..120
    const bool aok = (bm + arow) < M;
    const float* Ap = A + (size_t)(bm + arow) * K + acol;
    const float* Bp = W + (size_t)brow * N + bn + bcol;

    const int nst = K >> 4;

    // prologue: issue stages 0..STAGES-2
    #pragma unroll
    for (int s = 0; s < STAGES - 1; ++s) {
        const int k0 = s << 4;
        float* as = AsBase + s * AS_ELEMS;
        float* bs = BsBase + s * BS_ELEMS;
        cp_async16(&as[arow * AS_STRIDE + acol],     Ap + k0,     aok);
        cp_async16(&as[arow * AS_STRIDE + acol + 4], Ap + k0 + 4, aok);
        const float* bp = Bp + (size_t)k0 * N;
        cp_async16(&bs[brow * BS_STRIDE + bcol],     bp,     true);
        cp_async16(&bs[brow * BS_STRIDE + bcol + 4], bp + 4, true);
        cp_commit();
    }

    float acc[4][4][4];
    #pragma unroll
    for (int mi = 0; mi < 4; ++mi)
        #pragma unroll
        for (int ni = 0; ni < 4; ++ni)
            #pragma unroll
            for (int e = 0; e < 4; ++e) acc[mi][ni][e] = 0.f;

    for (int s = 0; s < nst; ++s) {
        cp_wait<STAGES - 2>();   // stage s resident
        __syncthreads();

        // issue stage s+STAGES-1 into the buffer just freed
        {
            const int sn = s + STAGES - 1;
            if (sn < nst) {
                const int buf = sn & (STAGES - 1);
                const int k0 = sn << 4;
                float* as = AsBase + buf * AS_ELEMS;
                float* bs = BsBase + buf * BS_ELEMS;
                cp_async16(&as[arow * AS_STRIDE + acol],     Ap + k0,     aok);
                cp_async16(&as[arow * AS_STRIDE + acol + 4], Ap + k0 + 4, aok);
                const float* bp = Bp + (size_t)k0 * N;
                cp_async16(&bs[brow * BS_STRIDE + bcol],     bp,     true);
                cp_async16(&bs[brow * BS_STRIDE + bcol + 4], bp + 4, true);
            }
            cp_commit();  // commit every iteration for uniform accounting
        }

        const float* asb = AsBase + (s & (STAGES - 1)) * AS_ELEMS;
        const float* bsb = BsBase + (s & (STAGES - 1)) * BS_ELEMS;
        #pragma unroll
        for (int kk = 0; kk < 16; kk += 8) {
            uint32_t a[4][4], b[4][2];
            #pragma unroll
            for (int mi = 0; mi < 4; ++mi) {
                int base = (wm + mi * 16 + g) * AS_STRIDE + kk + tg;
                a[mi][0] = __float_as_uint(asb[base]);
                a[mi][1] = __float_as_uint(asb[base + 8 * AS_STRIDE]);
                a[mi][2] = __float_as_uint(asb[base + 4]);
                a[mi][3] = __float_as_uint(asb[base + 8 * AS_STRIDE + 4]);
            }
            #pragma unroll
            for (int ni = 0; ni < 4; ++ni) {
                int c = wn + ni * 8 + g;
                b[ni][0] = __float_as_uint(bsb[(kk + tg) * BS_STRIDE + c]);
                b[ni][1] = __float_as_uint(bsb[(kk + tg + 4) * BS_STRIDE + c]);
            }
            #pragma unroll
            for (int mi = 0; mi < 4; ++mi)
                #pragma unroll
                for (int ni = 0; ni < 4; ++ni)
                    MMA_TF32(acc[mi][ni], a[mi], b[ni]);
        }
        __syncthreads();
    }

    // epilogue
    #pragma unroll
    for (int mi = 0; mi < 4; ++mi) {
        int r0 = bm + wm + mi * 16 + g;
        int r1 = r0 + 8;
        #pragma unroll
        for (int ni = 0; ni < 4; ++ni) {
            int col = bn + wn + ni * 8 + 2 * tg;
            float2 bb = *(const float2*)&bias[col];
            #pragma unroll
            for (int half = 0; half < 2; ++half) {
                int row = half ? r1 : r0;
                if (row >= M) continue;
                float vx = acc[mi][ni][half * 2 + 0] + bb.x;
                float vy = acc[mi][ni][half * 2 + 1] + bb.y;
                if (res) {
                    float2 rr = *(const float2*)&res[(size_t)row * N + col];
                    vx += rr.x; vy += rr.y;
                }
                if (RELU) { vx = fmaxf(vx, 0.f); vy = fmaxf(vy, 0.f); }
                if constexpr (sizeof(OutT) == 2) {
                    *(__half2*)&C[(size_t)row * N + col] = __floats2half2_rn(vx, vy);
                } else {
                    *(float2*)&C[(size_t)row * N + col] = make_float2(vx, vy);
                }
            }
        }
    }
}

// ---------------------------------------------------------------------------
// Deformable sampling with fused softmax.
// One warp per (token, head); lane = channel (DHEAD=32). value in fp16.
// ---------------------------------------------------------------------------
__global__ void sample_kernel(const __half* __restrict__ value,
                              const float* __restrict__ off,
                              const float* __restrict__ logits,
                              const float* __restrict__ ref,
                              float* __restrict__ out) {
    int gtid = blockIdx.x * blockDim.x + threadIdx.x;
    int gw = gtid >> 5;
    int lane = gtid & 31;
    if (gw >= TOK * NHEAD) return;
    int q = gw >> 3;
    int h = gw & 7;
    int b = q / LEN;

    const int HS[4] = {100, 50, 25, 13};
    const int ST[4] = {0, 10000, 12500, 13125};

    // fused softmax over 16 logits
    float lg = 0.f;
    if (lane < 16) lg = logits[(size_t)q * 128 + h * 16 + lane];
    float m = lg;
    #pragma unroll
    for (int o = 8; o > 0; o >>= 1) m = fmaxf(m, __shfl_xor_sync(0xffffffffu, m, o));
    float e = __expf(lg - m);
    float ssum = e;
    #pragma unroll
    for (int o = 8; o > 0; o >>= 1) ssum += __shfl_xor_sync(0xffffffffu, ssum, o);
    float wnorm = e / ssum;    // valid in lanes 0..15

    const float* offp = off + (size_t)q * 256 + h * 32;
    const float* refp = ref + (size_t)q * 8;
    const __half* vb  = value + (size_t)b * LEN * 256 + h * 32 + lane;

    float acc = 0.f;
    #pragma unroll
    for (int l = 0; l < 4; ++l) {
        const int Hl = HS[l];
        const int st = ST[l];
        float rx = refp[l * 2 + 0];
        float ry = refp[l * 2 + 1];
        #pragma unroll
        for (int p = 0; p < 4; ++p) {
            float ox = offp[(l * 4 + p) * 2 + 0];
            float oy = offp[(l * 4 + p) * 2 + 1];
            float w  = __shfl_sync(0xffffffffu, wnorm, l * 4 + p);
            float x = fmaf(rx, (float)Hl, ox - 0.5f);
            float y = fmaf(ry, (float)Hl, oy - 0.5f);
            float x0f = floorf(x), y0f = floorf(y);
            int x0 = (int)x0f, y0 = (int)y0f;
            float dx = x - x0f, dy = y - y0f;

            float mx0 = (x0 >= 0 && x0 < Hl) ? 1.f : 0.f;
            float mx1 = (x0 + 1 >= 0 && x0 + 1 < Hl) ? 1.f : 0.f;
            float my0 = (y0 >= 0 && y0 < Hl) ? 1.f : 0.f;
            float my1 = (y0 + 1 >= 0 && y0 + 1 < Hl) ? 1.f : 0.f;

            int x0c = min(max(x0, 0), Hl - 1);
            int x1c = min(max(x0 + 1, 0), Hl - 1);
            int y0c = min(max(y0, 0), Hl - 1);
            int y1c = min(max(y0 + 1, 0), Hl - 1);

            float w00 = (1.f - dx) * (1.f - dy) * mx0 * my0;
            float w10 = dx * (1.f - dy) * mx1 * my0;
            float w01 = (1.f - dx) * dy * mx0 * my1;
            float w11 = dx * dy * mx1 * my1;

            int r0 = st + y0c * Hl;
            int r1 = st + y1c * Hl;
            float v00 = __half2float(vb[(size_t)(r0 + x0c) * 256]);
            float v10 = __half2float(vb[(size_t)(r0 + x1c) * 256]);
            float v01 = __half2float(vb[(size_t)(r1 + x0c) * 256]);
            float v11 = __half2float(vb[(size_t)(r1 + x1c) * 256]);

            float s = w00 * v00 + w10 * v10 + w01 * v01 + w11 * v11;
            acc = fmaf(w, s, acc);
        }
    }
    out[(size_t)q * 256 + h * 32 + lane] = acc;
}

// ---------------------------------------------------------------------------
// LayerNorm over D=256: one warp per row
// ---------------------------------------------------------------------------
__global__ void ln_kernel(const float* __restrict__ x, const float* __restrict__ g,
                          const float* __restrict__ be, float* __restrict__ y,
                          int nrows) {
    int gtid = blockIdx.x * blockDim.x + threadIdx.x;
    int row = gtid >> 5;
    int lane = gtid & 31;
    if (row >= nrows) return;
    const float* p = x + (size_t)row * 256 + lane * 8;
    float v[8];
    *(float4*)&v[0] = *(const float4*)(p + 0);
    *(float4*)&v[4] = *(const float4*)(p + 4);
    float s = 0.f;
    #pragma unroll
    for (int i = 0; i < 8; ++i) s += v[i];
    #pragma unroll
    for (int o = 16; o > 0; o >>= 1) s += __shfl_xor_sync(0xffffffffu, s, o);
    float mean = s * (1.f / 256.f);
    float vs = 0.f;
    #pragma unroll
    for (int i = 0; i < 8; ++i) { float d = v[i] - mean; vs += d * d; }
    #pragma unroll
    for (int o = 16; o > 0; o >>= 1) vs += __shfl_xor_sync(0xffffffffu, vs, o);
    float rstd = rsqrtf(vs * (1.f / 256.f) + LN_EPS);
    float* q = y + (size_t)row * 256 + lane * 8;
    const float* gp = g + lane * 8;
    const float* bp = be + lane * 8;
    float go[8], bo[8];
    *(float4*)&go[0] = *(const float4*)(gp + 0);
    *(float4*)&go[4] = *(const float4*)(gp + 4);
    *(float4*)&bo[0] = *(const float4*)(bp + 0);
    *(float4*)&bo[4] = *(const float4*)(bp + 4);
    #pragma unroll
    for (int i = 0; i < 8; ++i) v[i] = (v[i] - mean) * rstd * go[i] + bo[i];
    *(float4*)(q + 0) = *(float4*)&v[0];
    *(float4*)(q + 4) = *(float4*)&v[4];
}

// ---------------------------------------------------------------------------
// Host launch
// ---------------------------------------------------------------------------
extern "C" void kernel_launch(void* const* d_in, const int* in_sizes, int n_in,
                              void* d_out, int out_size) {
    const float* src     = (const float*)d_in[0];
    const float* pos     = (const float*)d_in[1];
    const float* refpts  = (const float*)d_in[2];
    const float* W_value = (const float*)d_in[3];
    const float* b_value = (const float*)d_in[4];
    const float* W_off   = (const float*)d_in[5];
    const float* b_off   = (const float*)d_in[6];
    const float* W_attn  = (const float*)d_in[7];
    const float* b_attn  = (const float*)d_in[8];
    const float* W_out   = (const float*)d_in[9];
    const float* b_out   = (const float*)d_in[10];
    const float* W1      = (const float*)d_in[11];
    const float* b1      = (const float*)d_in[12];
    const float* W2      = (const float*)d_in[13];
    const float* b2      = (const float*)d_in[14];
    const float* g1      = (const float*)d_in[15];
    const float* be1     = (const float*)d_in[16];
    const float* g2      = (const float*)d_in[17];
    const float* be2     = (const float*)d_in[18];
    float* out = (float*)d_out;

    void* sp = nullptr;
    cudaGetSymbolAddress(&sp, g_scratch);
    float* base      = (float*)sp;
    float* g_query   = base;
    float* g_valuef  = g_query   + SZ256;   // reinterpreted as half
    float* g_off     = g_valuef  + SZ256;
    float* g_attnout = g_off     + SZ256;
    float* g_x1      = g_attnout + SZ256;
    float* g_ln1     = g_x1      + SZ256;
    float* g_x2      = g_ln1     + SZ256;
    float* g_attw    = g_x2      + SZ256;
    float* g_hid     = g_attw    + SZ128;
    __half* g_value_h = (__half*)g_valuef;

    // opt-in to >48KB dynamic smem (host-side attribute; idempotent; called
    // unconditionally every invocation — no static state)
    cudaFuncSetAttribute(gemm_tc<false, float>,
                         cudaFuncAttributeMaxDynamicSharedMemorySize, GEMM_SMEM_BYTES);
    cudaFuncSetAttribute(gemm_tc<true, float>,
                         cudaFuncAttributeMaxDynamicSharedMemorySize, GEMM_SMEM_BYTES);
    cudaFuncSetAttribute(gemm_tc<false, __half>,
                         cudaFuncAttributeMaxDynamicSharedMemorySize, GEMM_SMEM_BYTES);

    const int M = TOK;
    const int gy = (M + 127) / 128;   // 208

    // 1) query = src + pos
    {
        int n4 = (int)(SZ256 / 4);
        add_kernel<<<(n4 + 255) / 256, 256>>>(src, pos, g_query, n4);
    }
    // 2) value = src @ W_value + b_value  -> fp16
    gemm_tc<false, __half><<<dim3(2, gy), 256, GEMM_SMEM_BYTES>>>(src, W_value, b_value, nullptr, g_value_h, M, 256, 256);
    // 3) off = query @ W_off + b_off
    gemm_tc<false, float><<<dim3(2, gy), 256, GEMM_SMEM_BYTES>>>(g_query, W_off, b_off, nullptr, g_off, M, 256, 256);
    // 4) attw logits = query @ W_attn + b_attn (softmax fused into sampler)
    gemm_tc<false, float><<<dim3(1, gy), 256, GEMM_SMEM_BYTES>>>(g_query, W_attn, b_attn, nullptr, g_attw, M, 128, 256);
    // 5) deformable sampling (+ softmax)
    {
        int nthreads = TOK * NHEAD * 32;
        sample_kernel<<<(nthreads + 255) / 256, 256>>>(g_value_h, g_off, g_attw, refpts, g_attnout);
    }
    // 6) x1 = attnout @ W_out + b_out + src
    gemm_tc<false, float><<<dim3(2, gy), 256, GEMM_SMEM_BYTES>>>(g_attnout, W_out, b_out, src, g_x1, M, 256, 256);
    // 7) ln1 = LN(x1)
    {
        int nthreads = TOK * 32;
        ln_kernel<<<(nthreads + 255) / 256, 256>>>(g_x1, g1, be1, g_ln1, TOK);
    }
    // 8) hid = relu(ln1 @ W1 + b1)
    gemm_tc<true, float><<<dim3(8, gy), 256, GEMM_SMEM_BYTES>>>(g_ln1, W1, b1, nullptr, g_hid, M, 1024, 256);
    // 9) x2 = hid @ W2 + b2 + ln1
    gemm_tc<false, float><<<dim3(2, gy), 256, GEMM_SMEM_BYTES>>>(g_hid, W2, b2, g_ln1, g_x2, M, 256, 1024);
    // 10) out = LN(x2)
    {
        int nthreads = TOK * 32;
        ln_kernel<<<(nthreads + 255) / 256, 256>>>(g_x2, g2, be2, out, TOK);
    }
}